// round 1
// baseline (speedup 1.0000x reference)
#include <cuda_runtime.h>
#include <math.h>

#define NUM_A 64
#define NUM_T 32
#define NUM_B 64
#define NUM_V 12
#define DIM   512
#define M_ROWS (NUM_A*NUM_T)   /* 2048 */
#define N_ROWS (NUM_B*NUM_V)   /* 768  */
#define TAU_F 100.0f

// Scratch (no cudaMalloc allowed)
__device__ float g_tn[M_ROWS];           // 1/max(||t||,eps)
__device__ float g_vn[N_ROWS];           // 1/max(||v||,eps)
__device__ float g_sim[(size_t)M_ROWS*N_ROWS];  // 6.29 MB

typedef unsigned long long ull;

__device__ __forceinline__ ull pack2(float x, float y){
  ull r; asm("mov.b64 %0, {%1,%2};" : "=l"(r) : "f"(x), "f"(y)); return r;
}
__device__ __forceinline__ ull ffma2(ull a, ull b, ull c){
  ull d; asm("fma.rn.f32x2 %0, %1, %2, %3;" : "=l"(d) : "l"(a), "l"(b), "l"(c)); return d;
}
__device__ __forceinline__ float2 unpack2(ull p){
  float lo, hi; asm("mov.b64 {%0,%1}, %2;" : "=f"(lo), "=f"(hi) : "l"(p));
  return make_float2(lo, hi);
}

// ---------------- Kernel 1: inverse row norms ----------------
__global__ void norm_kernel(const float* __restrict__ tf, const float* __restrict__ vf){
  int gw   = (blockIdx.x*blockDim.x + threadIdx.x) >> 5;
  int lane = threadIdx.x & 31;
  if (gw >= M_ROWS + N_ROWS) return;
  const float4* src = (const float4*)((gw < M_ROWS) ? (tf + (size_t)gw*DIM)
                                                    : (vf + (size_t)(gw - M_ROWS)*DIM));
  float s = 0.f;
  #pragma unroll
  for (int i = 0; i < 4; i++){
    float4 x = src[lane + 32*i];
    s += x.x*x.x + x.y*x.y + x.z*x.z + x.w*x.w;
  }
  #pragma unroll
  for (int o = 16; o > 0; o >>= 1) s += __shfl_xor_sync(0xffffffffu, s, o);
  if (lane == 0){
    float inv = 1.0f / fmaxf(sqrtf(s), 1e-6f);
    if (gw < M_ROWS) g_tn[gw] = inv; else g_vn[gw - M_ROWS] = inv;
  }
}

// ---------------- Kernel 2: sim = (A @ B^T) * invnorms ----------------
// BM=BN=64, BK=32, 64 threads, 8x8 per thread, n-packed f32x2.
#define BK_ 32
#define LDSS 68   /* smem row stride (floats): 16B-aligned, conflict-free LDS.128 */

__global__ void __launch_bounds__(64) gemm_kernel(const float* __restrict__ Ag,
                                                  const float* __restrict__ Bg){
  __shared__ float As[BK_][LDSS];
  __shared__ float Bs[BK_][LDSS];
  const int tid = threadIdx.x;
  const int tx  = tid & 7;     // n-dim group (8 n each)
  const int ty  = tid >> 3;    // m-dim group (8 m each)
  const float* Ab = Ag + (size_t)blockIdx.x * 64 * DIM;
  const float* Bb = Bg + (size_t)blockIdx.y * 64 * DIM;

  ull c2[8][4];
  #pragma unroll
  for (int i = 0; i < 8; i++)
    #pragma unroll
    for (int j = 0; j < 4; j++) c2[i][j] = 0ull;

  for (int kt = 0; kt < DIM; kt += BK_){
    #pragma unroll
    for (int j = 0; j < 8; j++){
      int idx = tid + 64*j;            // 0..511
      int row = idx >> 3;              // 0..63
      int c4  = (idx & 7) << 2;        // 0,4,..,28
      float4 va = *(const float4*)(Ab + (size_t)row*DIM + kt + c4);
      As[c4+0][row] = va.x; As[c4+1][row] = va.y;
      As[c4+2][row] = va.z; As[c4+3][row] = va.w;
      float4 vb = *(const float4*)(Bb + (size_t)row*DIM + kt + c4);
      Bs[c4+0][row] = vb.x; Bs[c4+1][row] = vb.y;
      Bs[c4+2][row] = vb.z; Bs[c4+3][row] = vb.w;
    }
    __syncthreads();
    #pragma unroll
    for (int k = 0; k < BK_; k++){
      float4 b0 = *(const float4*)&Bs[k][tx*8];
      float4 b1 = *(const float4*)&Bs[k][tx*8 + 4];
      ull bb0 = pack2(b0.x, b0.y), bb1 = pack2(b0.z, b0.w);
      ull bb2 = pack2(b1.x, b1.y), bb3 = pack2(b1.z, b1.w);
      float4 a0 = *(const float4*)&As[k][ty*8];
      float4 a1 = *(const float4*)&As[k][ty*8 + 4];
      float av[8] = {a0.x, a0.y, a0.z, a0.w, a1.x, a1.y, a1.z, a1.w};
      #pragma unroll
      for (int i = 0; i < 8; i++){
        ull aa = pack2(av[i], av[i]);
        c2[i][0] = ffma2(aa, bb0, c2[i][0]);
        c2[i][1] = ffma2(aa, bb1, c2[i][1]);
        c2[i][2] = ffma2(aa, bb2, c2[i][2]);
        c2[i][3] = ffma2(aa, bb3, c2[i][3]);
      }
    }
    __syncthreads();
  }

  #pragma unroll
  for (int i = 0; i < 8; i++){
    int m = blockIdx.x*64 + ty*8 + i;
    float it = g_tn[m];
    float* dst = g_sim + (size_t)m*N_ROWS + blockIdx.y*64 + tx*8;
    #pragma unroll
    for (int j = 0; j < 4; j++){
      float2 v = unpack2(c2[i][j]);
      int n = blockIdx.y*64 + tx*8 + 2*j;
      dst[2*j]   = v.x * it * g_vn[n];
      dst[2*j+1] = v.y * it * g_vn[n+1];
    }
  }
}

// ---------------- Kernel 3: per-(a,b) softmax chain ----------------
__device__ __forceinline__ float wsum(float x){
  #pragma unroll
  for (int o = 16; o > 0; o >>= 1) x += __shfl_xor_sync(0xffffffffu, x, o);
  return x;
}
__device__ __forceinline__ float wmax(float x){
  #pragma unroll
  for (int o = 16; o > 0; o >>= 1) x = fmaxf(x, __shfl_xor_sync(0xffffffffu, x, o));
  return x;
}

__global__ void epi_kernel(const int* __restrict__ mask, float* __restrict__ out){
  const float NEG_INF = __int_as_float(0xff800000);
  int gw   = (blockIdx.x*blockDim.x + threadIdx.x) >> 5;  // 0..4095
  int lane = threadIdx.x & 31;                            // = t
  int a = gw >> 6, b = gw & 63;

  const float* sp = g_sim + (size_t)(a*NUM_T + lane)*N_ROWS + b*NUM_V;
  float4 s0 = *(const float4*)(sp);
  float4 s1 = *(const float4*)(sp + 4);
  float4 s2 = *(const float4*)(sp + 8);
  float sim[12] = {s0.x,s0.y,s0.z,s0.w, s1.x,s1.y,s1.z,s1.w, s2.x,s2.y,s2.z,s2.w};

  float msk = (float)mask[a*NUM_T + lane];
  float lg[12];
  #pragma unroll
  for (int j = 0; j < 12; j++) lg[j] = sim[j] * msk;

  // vps1 = softmax over v of TAU*logits; t2v[t] = sum_v vps1*sim
  float mx = TAU_F*lg[0];
  #pragma unroll
  for (int j = 1; j < 12; j++) mx = fmaxf(mx, TAU_F*lg[j]);
  float se = 0.f, tv = 0.f;
  #pragma unroll
  for (int j = 0; j < 12; j++){
    float e = expf(TAU_F*lg[j] - mx);
    se += e; tv += e * sim[j];
  }
  float t2v = tv / se;

  // tps1 = softmax over t of TAU*where(logits==0,-inf,logits); v2t[v]=sum_t tps1*sim
  float v2t[12];
  #pragma unroll
  for (int j = 0; j < 12; j++){
    float x  = (lg[j] == 0.f) ? NEG_INF : TAU_F*lg[j];
    float cm = wmax(x);                     // finite: >=1 valid token per text
    float e  = expf(x - cm);                // -inf -> 0
    float ss = wsum(e);
    v2t[j] = wsum((e / ss) * sim[j]);       // broadcast to all lanes
  }

  // tps2 = softmax over t of TAU*where(t2v==0,-inf,t2v)
  float x2  = (t2v == 0.f) ? NEG_INF : TAU_F*t2v;
  float m2  = wmax(x2);
  float e2  = expf(x2 - m2);
  float tps2 = e2 / wsum(e2);

  // vps2 = softmax over v of TAU*v2t (replicated per lane)
  float mv = TAU_F*v2t[0];
  #pragma unroll
  for (int j = 1; j < 12; j++) mv = fmaxf(mv, TAU_F*v2t[j]);
  float sv = 0.f, acc = 0.f;
  float w[12];
  #pragma unroll
  for (int j = 0; j < 12; j++){ w[j] = expf(TAU_F*v2t[j] - mv); sv += w[j]; }
  #pragma unroll
  for (int j = 0; j < 12; j++) acc += w[j] * sim[j];

  float res = wsum((acc / sv) * tps2);
  if (lane == 0) out[a*NUM_B + b] = res;
}

extern "C" void kernel_launch(void* const* d_in, const int* in_sizes, int n_in,
                              void* d_out, int out_size){
  const float* text  = (const float*)d_in[0];   // [64,32,512] f32
  const float* video = (const float*)d_in[1];   // [64,12,512] f32
  const int*   mask  = (const int*)d_in[2];     // [64,32] i32
  float* out = (float*)d_out;                   // [64,64] f32

  // 1) inverse norms: 2816 warps
  norm_kernel<<<(M_ROWS + N_ROWS + 7) / 8, 256>>>(text, video);

  // 2) sim GEMM: 2048x768x512, blocks 32x12
  dim3 g(M_ROWS/64, N_ROWS/64);
  gemm_kernel<<<g, 64>>>(text, video);

  // 3) epilogue: one warp per (a,b), 4096 warps
  epi_kernel<<<(NUM_A*NUM_B)/8, 256>>>(mask, out);
}

// round 2
// speedup vs baseline: 1.6296x; 1.6296x over previous
#include <cuda_runtime.h>
#include <cuda_bf16.h>
#include <math.h>

#define NUM_A 64
#define NUM_T 32
#define NUM_B 64
#define NUM_V 12
#define DIM   512
#define M_ROWS (NUM_A*NUM_T)   /* 2048 */
#define N_ROWS (NUM_B*NUM_V)   /* 768  */
#define KCAT  1536             /* [hi | hi | lo] vs [hi | lo | hi] */
#define TAU_F 100.0f

// ---------------- device scratch (no cudaMalloc allowed) ----------------
__device__ __nv_bfloat16 g_A[(size_t)M_ROWS*KCAT];   // 6.29 MB
__device__ __nv_bfloat16 g_B[(size_t)N_ROWS*KCAT];   // 2.36 MB
__device__ float g_part[2][(size_t)M_ROWS*N_ROWS];   // 12.6 MB (split-K partials)

// ---------------- PTX helpers ----------------
__device__ __forceinline__ void ldsm4(unsigned* r, const void* p){
  unsigned a = (unsigned)__cvta_generic_to_shared(p);
  asm volatile("ldmatrix.sync.aligned.m8n8.x4.shared.b16 {%0,%1,%2,%3}, [%4];"
    : "=r"(r[0]), "=r"(r[1]), "=r"(r[2]), "=r"(r[3]) : "r"(a));
}
__device__ __forceinline__ void ldsm2(unsigned* r, const void* p){
  unsigned a = (unsigned)__cvta_generic_to_shared(p);
  asm volatile("ldmatrix.sync.aligned.m8n8.x2.shared.b16 {%0,%1}, [%2];"
    : "=r"(r[0]), "=r"(r[1]) : "r"(a));
}
__device__ __forceinline__ void mma16816(float* c, const unsigned* a, const unsigned* b){
  asm volatile("mma.sync.aligned.m16n8k16.row.col.f32.bf16.bf16.f32 "
    "{%0,%1,%2,%3},{%4,%5,%6,%7},{%8,%9},{%0,%1,%2,%3};"
    : "+f"(c[0]), "+f"(c[1]), "+f"(c[2]), "+f"(c[3])
    : "r"(a[0]), "r"(a[1]), "r"(a[2]), "r"(a[3]), "r"(b[0]), "r"(b[1]));
}
__device__ __forceinline__ void cpasync16(void* s, const void* g){
  unsigned sa = (unsigned)__cvta_generic_to_shared(s);
  asm volatile("cp.async.cg.shared.global [%0],[%1],16;" :: "r"(sa), "l"(g));
}

// ---------------- Kernel 1: normalize + bf16 split + concat ----------------
// 256 threads = 2 rows x 128 threads. Each thread owns 4 consecutive floats.
__global__ void prep_kernel(const float* __restrict__ tf, const float* __restrict__ vf){
  int rsel = threadIdx.x >> 7;           // 0/1: which row in block
  int t    = threadIdx.x & 127;          // 0..127
  int r    = blockIdx.x*2 + rsel;        // 0..2815
  bool isText = r < M_ROWS;
  const float* src = isText ? (tf + (size_t)r*DIM) : (vf + (size_t)(r - M_ROWS)*DIM);
  float4 x = ((const float4*)src)[t];
  float ss = x.x*x.x + x.y*x.y + x.z*x.z + x.w*x.w;
  #pragma unroll
  for (int o = 16; o > 0; o >>= 1) ss += __shfl_xor_sync(0xffffffffu, ss, o);
  __shared__ float red[2][4];
  int w = (threadIdx.x >> 5) & 3;
  if ((threadIdx.x & 31) == 0) red[rsel][w] = ss;
  __syncthreads();
  float tot = red[rsel][0] + red[rsel][1] + red[rsel][2] + red[rsel][3];
  float inv = 1.0f / fmaxf(sqrtf(tot), 1e-6f);

  float xn[4] = {x.x*inv, x.y*inv, x.z*inv, x.w*inv};
  union { __nv_bfloat16 h[4]; uint2 u; } hi, lo;
  #pragma unroll
  for (int i = 0; i < 4; i++){
    hi.h[i] = __float2bfloat16(xn[i]);
    lo.h[i] = __float2bfloat16(xn[i] - __bfloat162float(hi.h[i]));
  }
  if (isText){
    __nv_bfloat16* base = g_A + (size_t)r*KCAT;
    ((uint2*)(base +        4*t))[0] = hi.u;   // seg0: hi
    ((uint2*)(base +  512 + 4*t))[0] = hi.u;   // seg1: hi (pairs with B lo)
    ((uint2*)(base + 1024 + 4*t))[0] = lo.u;   // seg2: lo (pairs with B hi)
  } else {
    __nv_bfloat16* base = g_B + (size_t)(r - M_ROWS)*KCAT;
    ((uint2*)(base +        4*t))[0] = hi.u;   // seg0: hi
    ((uint2*)(base +  512 + 4*t))[0] = lo.u;   // seg1: lo
    ((uint2*)(base + 1024 + 4*t))[0] = hi.u;   // seg2: hi
  }
}

// ---------------- Kernel 2: bf16 tensor-core GEMM, BM=BN=128, BK=32 ----------------
// 256 threads = 8 warps (2m x 4n), warp tile 64x32, split-K=2 via blockIdx.z.
#define BKB 32
#define NKI (768/BKB)   /* 24 k-iters per slice */
#define LDSB 40         /* bf16 smem row stride: conflict-free ldmatrix */

__global__ void __launch_bounds__(256) gemm_kernel(){
  __shared__ __nv_bfloat16 As[2][128][LDSB];
  __shared__ __nv_bfloat16 Bs[2][128][LDSB];
  const int tid  = threadIdx.x;
  const int lane = tid & 31;
  const int wid  = tid >> 5;
  const int wm   = wid >> 2;          // 0..1
  const int wn   = wid & 3;           // 0..3
  const int bm   = blockIdx.x * 128;
  const int bn   = blockIdx.y * 128;
  const int kbase = blockIdx.z * 768;

  // ldmatrix per-lane row/col selects
  const int arow = lane & 15, acol = (lane >> 4) << 3;   // A x4
  const int brow = lane & 7,  bcol = lane & 8;           // B x2

  float c[4][4][4];
  #pragma unroll
  for (int i = 0; i < 4; i++)
    #pragma unroll
    for (int j = 0; j < 4; j++)
      { c[i][j][0]=0.f; c[i][j][1]=0.f; c[i][j][2]=0.f; c[i][j][3]=0.f; }

  // tile loader: 128 rows x 32 cols per matrix; 16B chunks; 2 A + 2 B per thread
  auto load_tiles = [&](int it, int buf){
    int k0 = kbase + it*BKB;
    #pragma unroll
    for (int h = 0; h < 2; h++){
      int cidx = tid + 256*h;        // 0..511
      int row  = cidx >> 2;          // 0..127
      int seg  = (cidx & 3) << 3;    // 0,8,16,24
      cpasync16(&As[buf][row][seg], g_A + (size_t)(bm + row)*KCAT + k0 + seg);
      cpasync16(&Bs[buf][row][seg], g_B + (size_t)(bn + row)*KCAT + k0 + seg);
    }
    asm volatile("cp.async.commit_group;");
  };

  int buf = 0;
  load_tiles(0, buf);
  for (int it = 0; it < NKI; ++it){
    asm volatile("cp.async.wait_group 0;");
    __syncthreads();
    if (it + 1 < NKI) load_tiles(it + 1, buf ^ 1);
    #pragma unroll
    for (int ks = 0; ks < 2; ks++){
      int k0 = ks * 16;
      unsigned af[4][4], bf[4][2];
      #pragma unroll
      for (int mi = 0; mi < 4; mi++)
        ldsm4(af[mi], &As[buf][wm*64 + mi*16 + arow][k0 + acol]);
      #pragma unroll
      for (int nj = 0; nj < 4; nj++)
        ldsm2(bf[nj], &Bs[buf][wn*32 + nj*8 + brow][k0 + bcol]);
      #pragma unroll
      for (int mi = 0; mi < 4; mi++)
        #pragma unroll
        for (int nj = 0; nj < 4; nj++)
          mma16816(c[mi][nj], af[mi], bf[nj]);
    }
    buf ^= 1;
  }

  // epilogue: write partial sim tile
  float* outp = g_part[blockIdx.z];
  #pragma unroll
  for (int mi = 0; mi < 4; mi++){
    int r0 = bm + wm*64 + mi*16 + (lane >> 2);
    #pragma unroll
    for (int nj = 0; nj < 4; nj++){
      int col = bn + wn*32 + nj*8 + (lane & 3)*2;
      *(float2*)(outp + (size_t)r0*N_ROWS + col)       = make_float2(c[mi][nj][0], c[mi][nj][1]);
      *(float2*)(outp + (size_t)(r0+8)*N_ROWS + col)   = make_float2(c[mi][nj][2], c[mi][nj][3]);
    }
  }
}

// ---------------- Kernel 3: per-(a,b) softmax chain ----------------
__device__ __forceinline__ float wsum(float x){
  #pragma unroll
  for (int o = 16; o > 0; o >>= 1) x += __shfl_xor_sync(0xffffffffu, x, o);
  return x;
}
__device__ __forceinline__ float wmax(float x){
  #pragma unroll
  for (int o = 16; o > 0; o >>= 1) x = fmaxf(x, __shfl_xor_sync(0xffffffffu, x, o));
  return x;
}

__global__ void epi_kernel(const int* __restrict__ mask, float* __restrict__ out){
  const float NEG_INF = __int_as_float(0xff800000);
  int gw   = (blockIdx.x*blockDim.x + threadIdx.x) >> 5;  // 0..4095
  int lane = threadIdx.x & 31;                            // = t
  int a = gw >> 6, b = gw & 63;

  const float* s0p = g_part[0] + (size_t)(a*NUM_T + lane)*N_ROWS + b*NUM_V;
  const float* s1p = g_part[1] + (size_t)(a*NUM_T + lane)*N_ROWS + b*NUM_V;
  float sim[12];
  #pragma unroll
  for (int q = 0; q < 3; q++){
    float4 u = *(const float4*)(s0p + 4*q);
    float4 v = *(const float4*)(s1p + 4*q);
    sim[4*q+0] = u.x + v.x; sim[4*q+1] = u.y + v.y;
    sim[4*q+2] = u.z + v.z; sim[4*q+3] = u.w + v.w;
  }

  float msk = (float)mask[a*NUM_T + lane];
  float lg[12];
  #pragma unroll
  for (int j = 0; j < 12; j++) lg[j] = sim[j] * msk;

  // vps1 softmax over v; t2v[t]
  float mx = TAU_F*lg[0];
  #pragma unroll
  for (int j = 1; j < 12; j++) mx = fmaxf(mx, TAU_F*lg[j]);
  float se = 0.f, tv = 0.f;
  #pragma unroll
  for (int j = 0; j < 12; j++){
    float e = __expf(TAU_F*lg[j] - mx);
    se += e; tv += e * sim[j];
  }
  float t2v = tv / se;

  // tps1 masked softmax over t; v2t[v]
  float v2t[12];
  #pragma unroll
  for (int j = 0; j < 12; j++){
    float x  = (lg[j] == 0.f) ? NEG_INF : TAU_F*lg[j];
    float cm = wmax(x);
    float e  = __expf(x - cm);
    float ss = wsum(e);
    v2t[j] = wsum((e / ss) * sim[j]);
  }

  // tps2 masked softmax over t of t2v
  float x2  = (t2v == 0.f) ? NEG_INF : TAU_F*t2v;
  float m2  = wmax(x2);
  float e2  = __expf(x2 - m2);
  float tps2 = e2 / wsum(e2);

  // vps2 softmax over v of v2t
  float mv = TAU_F*v2t[0];
  #pragma unroll
  for (int j = 1; j < 12; j++) mv = fmaxf(mv, TAU_F*v2t[j]);
  float sv = 0.f, acc = 0.f;
  #pragma unroll
  for (int j = 0; j < 12; j++){
    float w = __expf(TAU_F*v2t[j] - mv);
    sv += w; acc += w * sim[j];
  }

  float res = wsum((acc / sv) * tps2);
  if (lane == 0) out[a*NUM_B + b] = res;
}

extern "C" void kernel_launch(void* const* d_in, const int* in_sizes, int n_in,
                              void* d_out, int out_size){
  const float* text  = (const float*)d_in[0];   // [64,32,512] f32
  const float* video = (const float*)d_in[1];   // [64,12,512] f32
  const int*   mask  = (const int*)d_in[2];     // [64,32] i32
  float* out = (float*)d_out;                   // [64,64] f32

  prep_kernel<<<(M_ROWS + N_ROWS)/2, 256>>>(text, video);
  dim3 g(M_ROWS/128, N_ROWS/128, 2);
  gemm_kernel<<<g, 256>>>();
  epi_kernel<<<(NUM_A*NUM_B)/8, 256>>>(mask, out);
}

// round 5
// speedup vs baseline: 1.9923x; 1.2226x over previous
#include <cuda_runtime.h>
#include <cuda_bf16.h>
#include <math.h>
#include <stdint.h>

#define NUM_A 64
#define NUM_T 32
#define NUM_B 64
#define NUM_V 12
#define DIM   512
#define M_ROWS 2048
#define N_ROWS 768
#define KP    1024            /* packed bf16 cols per row: [hi(512) | lo(512)] */
#define TAU_F 100.0f

// ---------------- device scratch ----------------
__device__ __nv_bfloat16 g_A [(size_t)M_ROWS*KP];    // 4.19 MB
__device__ __nv_bfloat16 g_Bm[(size_t)N_ROWS*KP];    // 1.57 MB
__device__ float g_part[3][(size_t)M_ROWS*N_ROWS];   // 18.9 MB (hh, hl, lh partials)

// ---------------- PTX helpers (HMMA path only — NO tcgen05) ----------------
static __device__ __forceinline__ void ldsm4(unsigned* r, const void* p){
  unsigned a = (unsigned)__cvta_generic_to_shared(p);
  asm volatile("ldmatrix.sync.aligned.m8n8.x4.shared.b16 {%0,%1,%2,%3}, [%4];"
    : "=r"(r[0]), "=r"(r[1]), "=r"(r[2]), "=r"(r[3]) : "r"(a));
}
static __device__ __forceinline__ void mma16816(float* c, const unsigned* a, const unsigned* b){
  asm volatile("mma.sync.aligned.m16n8k16.row.col.f32.bf16.bf16.f32 "
    "{%0,%1,%2,%3},{%4,%5,%6,%7},{%8,%9},{%0,%1,%2,%3};"
    : "+f"(c[0]), "+f"(c[1]), "+f"(c[2]), "+f"(c[3])
    : "r"(a[0]), "r"(a[1]), "r"(a[2]), "r"(a[3]), "r"(b[0]), "r"(b[1]));
}
static __device__ __forceinline__ void cp16(void* s, const void* g){
  unsigned sa = (unsigned)__cvta_generic_to_shared(s);
  asm volatile("cp.async.cg.shared.global [%0],[%1],16;" :: "r"(sa), "l"(g));
}

// ---------------- Kernel 1: normalize + bf16 hi/lo split (1 block per row) ----------------
__global__ void __launch_bounds__(128) prep_kernel(const float* __restrict__ tf,
                                                   const float* __restrict__ vf){
  __shared__ float red[4];
  int r = blockIdx.x;                        // 0..2815
  int tid = threadIdx.x;                     // 0..127
  bool isText = r < M_ROWS;
  const float4* src = (const float4*)(isText ? tf + (size_t)r*DIM
                                             : vf + (size_t)(r - M_ROWS)*DIM);
  float4 x = src[tid];
  float ss = x.x*x.x + x.y*x.y + x.z*x.z + x.w*x.w;
  #pragma unroll
  for (int o = 16; o > 0; o >>= 1) ss += __shfl_xor_sync(0xffffffffu, ss, o);
  if ((tid & 31) == 0) red[tid >> 5] = ss;
  __syncthreads();
  float tot = red[0] + red[1] + red[2] + red[3];
  float inv = 1.0f / fmaxf(sqrtf(tot), 1e-6f);

  float f[4] = {x.x*inv, x.y*inv, x.z*inv, x.w*inv};
  union { __nv_bfloat16 h[4]; uint2 u2; } hi, lo;
  #pragma unroll
  for (int j = 0; j < 4; j++){
    hi.h[j] = __float2bfloat16(f[j]);
    lo.h[j] = __float2bfloat16(f[j] - __bfloat162float(hi.h[j]));
  }
  __nv_bfloat16* dst = isText ? (g_A + (size_t)r*KP) : (g_Bm + (size_t)(r - M_ROWS)*KP);
  *(uint2*)(dst + 4*tid)       = hi.u2;
  *(uint2*)(dst + 512 + 4*tid) = lo.u2;
}

// ---------------- Kernel 2: bf16 HMMA GEMM, BM=BN=128, BK=32, 3-stage, split-K=3 ----------------
#define BKB   32
#define NKI   16              /* 512 / 32 k-iters per slice */
#define LDSB  40              /* bf16 smem row stride: conflict-free ldmatrix (validated R2) */
#define STG_ELE (128*LDSB)    /* elems per matrix per stage */
#define GSMEM_G (3*2*STG_ELE*2)  /* 61440 B */

__global__ void __launch_bounds__(256, 2) gemm_kernel(){
  extern __shared__ __nv_bfloat16 sh[];
  __nv_bfloat16* As = sh;                 // [3][128][LDSB]
  __nv_bfloat16* Bs = sh + 3*STG_ELE;     // [3][128][LDSB]
  const int tid  = threadIdx.x;
  const int lane = tid & 31;
  const int wid  = tid >> 5;
  const int wm   = wid >> 2;              // 0..1
  const int wn   = wid & 3;               // 0..3
  const int bm   = blockIdx.x * 128;
  const int bn   = blockIdx.y * 128;
  const int z    = blockIdx.z;            // 0:hh 1:hl 2:lh
  const int Aoff = (z == 2) ? 512 : 0;
  const int Boff = (z == 1) ? 512 : 0;

  // ldmatrix lane selects (validated in R2)
  const int arow = lane & 15, acol = (lane >> 4) << 3;              // A x4
  const int brow8 = ((lane >> 4) << 3) + (lane & 7);                // B x4: row within 16
  const int bcol  = ((lane >> 3) & 1) << 3;                         // B x4: k half

  float c[4][4][4];
  #pragma unroll
  for (int i = 0; i < 4; i++)
    #pragma unroll
    for (int j = 0; j < 4; j++)
      { c[i][j][0]=0.f; c[i][j][1]=0.f; c[i][j][2]=0.f; c[i][j][3]=0.f; }

  // stage loader: 128 rows x 32 cols per matrix; 2 A + 2 B cp16 per thread
  auto load_stage = [&](int it, int s){
    const __nv_bfloat16* Abase = g_A  + (size_t)bm*KP + Aoff + it*BKB;
    const __nv_bfloat16* Bbase = g_Bm + (size_t)bn*KP + Boff + it*BKB;
    #pragma unroll
    for (int h = 0; h < 2; h++){
      int cidx = tid + 256*h;        // 0..511
      int row  = cidx >> 2;          // 0..127
      int seg  = (cidx & 3) << 3;    // 0,8,16,24
      cp16(As + s*STG_ELE + row*LDSB + seg, Abase + (size_t)row*KP + seg);
      cp16(Bs + s*STG_ELE + row*LDSB + seg, Bbase + (size_t)row*KP + seg);
    }
    asm volatile("cp.async.commit_group;" ::: "memory");
  };

  load_stage(0, 0);
  load_stage(1, 1);

  #pragma unroll
  for (int it = 0; it < NKI; ++it){
    const int s = it % 3;
    if (it < NKI - 1) asm volatile("cp.async.wait_group 1;" ::: "memory");
    else              asm volatile("cp.async.wait_group 0;" ::: "memory");
    __syncthreads();
    if (it + 2 < NKI) load_stage(it + 2, (it + 2) % 3);

    const __nv_bfloat16* Asb = As + s*STG_ELE;
    const __nv_bfloat16* Bsb = Bs + s*STG_ELE;
    #pragma unroll
    for (int ks = 0; ks < 2; ks++){
      const int k0 = ks * 16;
      unsigned af[4][4], bf[2][4];
      #pragma unroll
      for (int mi = 0; mi < 4; mi++)
        ldsm4(af[mi], Asb + (wm*64 + mi*16 + arow)*LDSB + k0 + acol);
      #pragma unroll
      for (int p = 0; p < 2; p++)
        ldsm4(bf[p], Bsb + (wn*32 + p*16 + brow8)*LDSB + k0 + bcol);
      #pragma unroll
      for (int mi = 0; mi < 4; mi++)
        #pragma unroll
        for (int p = 0; p < 2; p++){
          mma16816(c[mi][2*p],   af[mi], &bf[p][0]);
          mma16816(c[mi][2*p+1], af[mi], &bf[p][2]);
        }
    }
    __syncthreads();
  }

  // epilogue: write partial tile row-major (validated R2 mapping)
  float* outp = g_part[z];
  #pragma unroll
  for (int mi = 0; mi < 4; mi++){
    int r0 = bm + wm*64 + mi*16 + (lane >> 2);
    #pragma unroll
    for (int nj = 0; nj < 4; nj++){
      int col = bn + wn*32 + nj*8 + (lane & 3)*2;
      *(float2*)(outp + (size_t)r0*N_ROWS + col)     = make_float2(c[mi][nj][0], c[mi][nj][1]);
      *(float2*)(outp + (size_t)(r0+8)*N_ROWS + col) = make_float2(c[mi][nj][2], c[mi][nj][3]);
    }
  }
}

// ---------------- Kernel 3: per-(a,b) softmax chain ----------------
static __device__ __forceinline__ float wsum(float x){
  #pragma unroll
  for (int o = 16; o > 0; o >>= 1) x += __shfl_xor_sync(0xffffffffu, x, o);
  return x;
}
static __device__ __forceinline__ float wmax(float x){
  #pragma unroll
  for (int o = 16; o > 0; o >>= 1) x = fmaxf(x, __shfl_xor_sync(0xffffffffu, x, o));
  return x;
}

__global__ void __launch_bounds__(256) epi_kernel(const int* __restrict__ mask,
                                                  float* __restrict__ out){
  const float NEG_INF = __int_as_float(0xff800000);
  int gw   = (blockIdx.x*blockDim.x + threadIdx.x) >> 5;  // 0..4095
  int lane = threadIdx.x & 31;                            // = t
  int a = gw >> 6, b = gw & 63;

  size_t off = (size_t)(a*NUM_T + lane)*N_ROWS + b*NUM_V;
  float sim[12];
  #pragma unroll
  for (int q = 0; q < 3; q++){
    float4 u0 = *(const float4*)(g_part[0] + off + 4*q);
    float4 u1 = *(const float4*)(g_part[1] + off + 4*q);
    float4 u2 = *(const float4*)(g_part[2] + off + 4*q);
    sim[4*q+0] = u0.x + u1.x + u2.x;
    sim[4*q+1] = u0.y + u1.y + u2.y;
    sim[4*q+2] = u0.z + u1.z + u2.z;
    sim[4*q+3] = u0.w + u1.w + u2.w;
  }

  float msk = (float)mask[a*NUM_T + lane];
  float lg[12];
  #pragma unroll
  for (int j = 0; j < 12; j++) lg[j] = sim[j] * msk;

  // vps1 softmax over v; t2v[t]
  float mx = TAU_F*lg[0];
  #pragma unroll
  for (int j = 1; j < 12; j++) mx = fmaxf(mx, TAU_F*lg[j]);
  float se = 0.f, tv = 0.f;
  #pragma unroll
  for (int j = 0; j < 12; j++){
    float e = __expf(TAU_F*lg[j] - mx);
    se += e; tv += e * sim[j];
  }
  float t2v = tv / se;

  // tps1 masked softmax over t; v2t[v]
  float v2t[12];
  #pragma unroll
  for (int j = 0; j < 12; j++){
    float x  = (lg[j] == 0.f) ? NEG_INF : TAU_F*lg[j];
    float cm = wmax(x);
    float e  = __expf(x - cm);
    float ssum = wsum(e);
    v2t[j] = wsum((e / ssum) * sim[j]);
  }

  // tps2 masked softmax over t of t2v
  float x2  = (t2v == 0.f) ? NEG_INF : TAU_F*t2v;
  float m2  = wmax(x2);
  float e2  = __expf(x2 - m2);
  float tps2 = e2 / wsum(e2);

  // vps2 softmax over v of v2t
  float mv = TAU_F*v2t[0];
  #pragma unroll
  for (int j = 1; j < 12; j++) mv = fmaxf(mv, TAU_F*v2t[j]);
  float sv = 0.f, acc = 0.f;
  #pragma unroll
  for (int j = 0; j < 12; j++){
    float w = __expf(TAU_F*v2t[j] - mv);
    sv += w; acc += w * sim[j];
  }

  float res = wsum((acc / sv) * tps2);
  if (lane == 0) out[a*NUM_B + b] = res;
}

// ---------------- launch ----------------
extern "C" void kernel_launch(void* const* d_in, const int* in_sizes, int n_in,
                              void* d_out, int out_size){
  const float* text  = (const float*)d_in[0];   // [64,32,512] f32
  const float* video = (const float*)d_in[1];   // [64,12,512] f32
  const int*   mask  = (const int*)d_in[2];     // [64,32] i32
  float* out = (float*)d_out;                   // [64,64] f32

  static int smem_set = 0;
  if (!smem_set){
    cudaFuncSetAttribute(gemm_kernel, cudaFuncAttributeMaxDynamicSharedMemorySize, GSMEM_G);
    smem_set = 1;
  }

  prep_kernel<<<M_ROWS + N_ROWS, 128>>>(text, video);
  dim3 g(M_ROWS/128, N_ROWS/128, 3);
  gemm_kernel<<<g, 256, GSMEM_G>>>();
  epi_kernel<<<(NUM_A*NUM_B)/8, 256>>>(mask, out);
}

// round 7
// speedup vs baseline: 2.2702x; 1.1395x over previous
#include <cuda_runtime.h>
#include <cuda_bf16.h>
#include <math.h>
#include <stdint.h>

#define NUM_A 64
#define NUM_T 32
#define NUM_B 64
#define NUM_V 12
#define DIM   512
#define M_ROWS 2048
#define N_ROWS 768
#define KP    1024            /* packed bf16 cols per row: [hi(512) | lo(512)] */
#define TAU_F 100.0f

// ---------------- device scratch ----------------
__device__ __nv_bfloat16 g_A [(size_t)M_ROWS*KP];    // 4.19 MB
__device__ __nv_bfloat16 g_Bm[(size_t)N_ROWS*KP];    // 1.57 MB
__device__ float g_part[3][(size_t)N_ROWS*M_ROWS];   // 18.9 MB, TRANSPOSED [n][m]

// ---------------- PTX helpers (HMMA path only — NO tcgen05) ----------------
static __device__ __forceinline__ void ldsm4(unsigned* r, const void* p){
  unsigned a = (unsigned)__cvta_generic_to_shared(p);
  asm volatile("ldmatrix.sync.aligned.m8n8.x4.shared.b16 {%0,%1,%2,%3}, [%4];"
    : "=r"(r[0]), "=r"(r[1]), "=r"(r[2]), "=r"(r[3]) : "r"(a));
}
static __device__ __forceinline__ void mma16816(float* c, const unsigned* a, const unsigned* b){
  asm volatile("mma.sync.aligned.m16n8k16.row.col.f32.bf16.bf16.f32 "
    "{%0,%1,%2,%3},{%4,%5,%6,%7},{%8,%9},{%0,%1,%2,%3};"
    : "+f"(c[0]), "+f"(c[1]), "+f"(c[2]), "+f"(c[3])
    : "r"(a[0]), "r"(a[1]), "r"(a[2]), "r"(a[3]), "r"(b[0]), "r"(b[1]));
}
static __device__ __forceinline__ void cp16(void* s, const void* g){
  unsigned sa = (unsigned)__cvta_generic_to_shared(s);
  asm volatile("cp.async.cg.shared.global [%0],[%1],16;" :: "r"(sa), "l"(g));
}

// ---------------- Kernel 1: normalize + bf16 hi/lo split (warp per row, MLP=4) ----------------
__global__ void __launch_bounds__(512) prep_kernel(const float* __restrict__ tf,
                                                   const float* __restrict__ vf){
  int w    = threadIdx.x >> 5;               // 0..15
  int lane = threadIdx.x & 31;
  int r    = blockIdx.x*16 + w;              // 0..2815
  bool isText = r < M_ROWS;
  const float4* src = (const float4*)(isText ? tf + (size_t)r*DIM
                                             : vf + (size_t)(r - M_ROWS)*DIM);
  float4 x[4];
  float ss = 0.f;
  #pragma unroll
  for (int i = 0; i < 4; i++){
    x[i] = src[lane + 32*i];                 // 4 independent LDG.128 in flight
    ss += x[i].x*x[i].x + x[i].y*x[i].y + x[i].z*x[i].z + x[i].w*x[i].w;
  }
  #pragma unroll
  for (int o = 16; o > 0; o >>= 1) ss += __shfl_xor_sync(0xffffffffu, ss, o);
  float inv = 1.0f / fmaxf(sqrtf(ss), 1e-6f);

  __nv_bfloat16* dst = isText ? (g_A + (size_t)r*KP) : (g_Bm + (size_t)(r - M_ROWS)*KP);
  #pragma unroll
  for (int i = 0; i < 4; i++){
    float f[4] = {x[i].x*inv, x[i].y*inv, x[i].z*inv, x[i].w*inv};
    union { __nv_bfloat16 h[4]; uint2 u2; } hi, lo;
    #pragma unroll
    for (int j = 0; j < 4; j++){
      hi.h[j] = __float2bfloat16(f[j]);
      lo.h[j] = __float2bfloat16(f[j] - __bfloat162float(hi.h[j]));
    }
    int col4 = lane + 32*i;
    *(uint2*)(dst + 4*col4)       = hi.u2;
    *(uint2*)(dst + 512 + 4*col4) = lo.u2;
  }
}

// ---------------- Kernel 2: bf16 HMMA GEMM, BM=BN=128, BK=64, 3-stage, split-K=3 ----------------
#define BKB   64
#define NKI   8               /* 512 / 64 k-iters per slice */
#define LDSB  72              /* bf16 smem row stride: 144B ≡ 16 mod 128 -> conflict-free ldmatrix */
#define STG_ELE (128*LDSB)    /* elems per matrix per stage = 9216 */
#define GSMEM_G (3*2*STG_ELE*2)  /* 110592 B */

__global__ void __launch_bounds__(256, 2) gemm_kernel(){
  extern __shared__ __nv_bfloat16 sh[];
  __nv_bfloat16* As = sh;                 // [3][128][LDSB]
  __nv_bfloat16* Bs = sh + 3*STG_ELE;     // [3][128][LDSB]
  const int tid  = threadIdx.x;
  const int lane = tid & 31;
  const int wid  = tid >> 5;
  const int wm   = wid >> 2;              // 0..1
  const int wn   = wid & 3;               // 0..3
  const int bm   = blockIdx.x * 128;
  const int bn   = blockIdx.y * 128;
  const int z    = blockIdx.z;            // 0:hh 1:hl 2:lh
  const int Aoff = (z == 2) ? 512 : 0;
  const int Boff = (z == 1) ? 512 : 0;

  // ldmatrix lane selects (validated R2/R5)
  const int arow = lane & 15, acol = (lane >> 4) << 3;              // A x4
  const int brow8 = ((lane >> 4) << 3) + (lane & 7);                // B x4: row within 16
  const int bcol  = ((lane >> 3) & 1) << 3;                         // B x4: k half

  float c[4][4][4];
  #pragma unroll
  for (int i = 0; i < 4; i++)
    #pragma unroll
    for (int j = 0; j < 4; j++)
      { c[i][j][0]=0.f; c[i][j][1]=0.f; c[i][j][2]=0.f; c[i][j][3]=0.f; }

  // stage loader: 128 rows x 64 cols per matrix; 4 A + 4 B cp16 per thread
  auto load_stage = [&](int it, int s){
    const __nv_bfloat16* Abase = g_A  + (size_t)bm*KP + Aoff + it*BKB;
    const __nv_bfloat16* Bbase = g_Bm + (size_t)bn*KP + Boff + it*BKB;
    #pragma unroll
    for (int h = 0; h < 4; h++){
      int cidx = tid + 256*h;        // 0..1023
      int row  = cidx >> 3;          // 0..127
      int seg  = (cidx & 7) << 3;    // 0,8,...,56
      cp16(As + s*STG_ELE + row*LDSB + seg, Abase + (size_t)row*KP + seg);
      cp16(Bs + s*STG_ELE + row*LDSB + seg, Bbase + (size_t)row*KP + seg);
    }
    asm volatile("cp.async.commit_group;" ::: "memory");
  };

  load_stage(0, 0);
  load_stage(1, 1);

  #pragma unroll
  for (int it = 0; it < NKI; ++it){
    const int s = it % 3;
    if (it < NKI - 1) asm volatile("cp.async.wait_group 1;" ::: "memory");
    else              asm volatile("cp.async.wait_group 0;" ::: "memory");
    __syncthreads();
    if (it + 2 < NKI) load_stage(it + 2, (it + 2) % 3);

    const __nv_bfloat16* Asb = As + s*STG_ELE;
    const __nv_bfloat16* Bsb = Bs + s*STG_ELE;
    #pragma unroll
    for (int ks = 0; ks < 4; ks++){
      const int k0 = ks * 16;
      unsigned af[4][4], bf[2][4];
      #pragma unroll
      for (int mi = 0; mi < 4; mi++)
        ldsm4(af[mi], Asb + (wm*64 + mi*16 + arow)*LDSB + k0 + acol);
      #pragma unroll
      for (int p = 0; p < 2; p++)
        ldsm4(bf[p], Bsb + (wn*32 + p*16 + brow8)*LDSB + k0 + bcol);
      #pragma unroll
      for (int mi = 0; mi < 4; mi++)
        #pragma unroll
        for (int p = 0; p < 2; p++){
          mma16816(c[mi][2*p],   af[mi], &bf[p][0]);
          mma16816(c[mi][2*p+1], af[mi], &bf[p][2]);
        }
    }
    __syncthreads();
  }

  // epilogue: write partial tile TRANSPOSED [n][m]
  float* outp = g_part[z];
  #pragma unroll
  for (int mi = 0; mi < 4; mi++){
    int r0 = bm + wm*64 + mi*16 + (lane >> 2);
    #pragma unroll
    for (int nj = 0; nj < 4; nj++){
      int col = bn + wn*32 + nj*8 + (lane & 3)*2;
      outp[(size_t)col*M_ROWS     + r0]     = c[mi][nj][0];
      outp[(size_t)(col+1)*M_ROWS + r0]     = c[mi][nj][1];
      outp[(size_t)col*M_ROWS     + r0 + 8] = c[mi][nj][2];
      outp[(size_t)(col+1)*M_ROWS + r0 + 8] = c[mi][nj][3];
    }
  }
}

// ---------------- Kernel 3: per-(a,b) softmax chain ----------------
static __device__ __forceinline__ float wsum(float x){
  #pragma unroll
  for (int o = 16; o > 0; o >>= 1) x += __shfl_xor_sync(0xffffffffu, x, o);
  return x;
}
static __device__ __forceinline__ float wmax(float x){
  #pragma unroll
  for (int o = 16; o > 0; o >>= 1) x = fmaxf(x, __shfl_xor_sync(0xffffffffu, x, o));
  return x;
}

__global__ void __launch_bounds__(256) epi_kernel(const int* __restrict__ mask,
                                                  float* __restrict__ out){
  const float NEG_INF = __int_as_float(0xff800000);
  int gw   = (blockIdx.x*blockDim.x + threadIdx.x) >> 5;  // 0..4095
  int lane = threadIdx.x & 31;                            // = t
  int a = gw >> 6, b = gw & 63;

  // transposed layout -> lane-coalesced loads
  size_t base = (size_t)(b*NUM_V)*M_ROWS + a*NUM_T + lane;
  float sim[12];
  #pragma unroll
  for (int j = 0; j < 12; j++){
    sim[j] = g_part[0][base + (size_t)j*M_ROWS]
           + g_part[1][base + (size_t)j*M_ROWS]
           + g_part[2][base + (size_t)j*M_ROWS];
  }

  float msk = (float)mask[a*NUM_T + lane];
  float lg[12];
  #pragma unroll
  for (int j = 0; j < 12; j++) lg[j] = sim[j] * msk;

  // vps1 softmax over v; t2v[t]
  float mx = TAU_F*lg[0];
  #pragma unroll
  for (int j = 1; j < 12; j++) mx = fmaxf(mx, TAU_F*lg[j]);
  float se = 0.f, tv = 0.f;
  #pragma unroll
  for (int j = 0; j < 12; j++){
    float e = __expf(TAU_F*lg[j] - mx);
    se += e; tv += e * sim[j];
  }
  float t2v = tv / se;

  // tps1 masked softmax over t; v2t[v]
  float v2t[12];
  #pragma unroll
  for (int j = 0; j < 12; j++){
    float x  = (lg[j] == 0.f) ? NEG_INF : TAU_F*lg[j];
    float cm = wmax(x);
    float e  = __expf(x - cm);
    float ssum = wsum(e);
    v2t[j] = wsum((e / ssum) * sim[j]);
  }

  // tps2 masked softmax over t of t2v
  float x2  = (t2v == 0.f) ? NEG_INF : TAU_F*t2v;
  float m2  = wmax(x2);
  float e2  = __expf(x2 - m2);
  float tps2 = e2 / wsum(e2);

  // vps2 softmax over v of v2t
  float mv = TAU_F*v2t[0];
  #pragma unroll
  for (int j = 1; j < 12; j++) mv = fmaxf(mv, TAU_F*v2t[j]);
  float sv = 0.f, acc = 0.f;
  #pragma unroll
  for (int j = 0; j < 12; j++){
    float w = __expf(TAU_F*v2t[j] - mv);
    sv += w; acc += w * sim[j];
  }

  float res = wsum((acc / sv) * tps2);
  if (lane == 0) out[a*NUM_B + b] = res;
}

// ---------------- launch ----------------
extern "C" void kernel_launch(void* const* d_in, const int* in_sizes, int n_in,
                              void* d_out, int out_size){
  const float* text  = (const float*)d_in[0];   // [64,32,512] f32
  const float* video = (const float*)d_in[1];   // [64,12,512] f32
  const int*   mask  = (const int*)d_in[2];     // [64,32] i32
  float* out = (float*)d_out;                   // [64,64] f32

  cudaFuncSetAttribute(gemm_kernel, cudaFuncAttributeMaxDynamicSharedMemorySize, GSMEM_G);

  prep_kernel<<<(M_ROWS + N_ROWS)/16, 512>>>(text, video);
  dim3 g(M_ROWS/128, N_ROWS/128, 3);
  gemm_kernel<<<g, 256, GSMEM_G>>>();
  epi_kernel<<<(NUM_A*NUM_B)/8, 256>>>(mask, out);
}